// round 5
// baseline (speedup 1.0000x reference)
#include <cuda_runtime.h>

#define CDIM 3755
#define RDIM 214
#define SDIM 13
#define SCBDIM 30
#define STDIM 6
#define HDIM 64
#define KTOP 20
#define CAP 512
#define NT 256
#define NEGF 3.4e38f

__device__ __forceinline__ unsigned f2key(float x) {
    unsigned u = __float_as_uint(x);
    return (u & 0x80000000u) ? ~u : (u | 0x80000000u);
}
__device__ __forceinline__ float key2f(unsigned k) {
    return __uint_as_float((k & 0x80000000u) ? (k & 0x7FFFFFFFu) : ~k);
}
__device__ __forceinline__ unsigned long long packvi(float v, int j) {
    return ((unsigned long long)f2key(v) << 32) | (unsigned)(0x7FFFFFFF - j);
}

__device__ __forceinline__ void append1(float v, int j, float t, int lane, unsigned lm,
                                        int* pn, unsigned long long* cp) {
    bool pr = v >= t;
    unsigned m = __ballot_sync(~0u, pr);
    if (!m) return;
    int ldr = __ffs(m) - 1;
    int bs = 0;
    if (lane == ldr) bs = atomicAdd(pn, __popc(m));
    bs = __shfl_sync(~0u, bs, ldr);
    if (pr) {
        int pos = bs + __popc(m & lm);
        if (pos < CAP) cp[pos] = packvi(v, j);
    }
}

__global__ void __launch_bounds__(NT) rerank_kernel(
    const float* __restrict__ charL, const float* __restrict__ radL,
    const float* __restrict__ structL, const float* __restrict__ scL,
    const float* __restrict__ styL, const int* __restrict__ rmask,
    const int* __restrict__ slab, const int* __restrict__ sclab,
    const float* __restrict__ sig, const float* __restrict__ W1,
    const float* __restrict__ b1, const float* __restrict__ W2,
    const float* __restrict__ b2, const float* __restrict__ rwp,
    float* __restrict__ out)
{
    __shared__ unsigned long long cpack[CAP];
    __shared__ float rps[RDIM];
    __shared__ float w1s[6 * HDIM], b1sh[HDIM], w2sh[HDIM];
    __shared__ float sprob[SDIM], predn[STDIM];
    __shared__ float feat6[KTOP][6];
    __shared__ int tIdx[KTOP];
    __shared__ float tVal[KTOP];
    __shared__ float redm[8], reds[8], redt[8];
    __shared__ unsigned long long red64[8];
    __shared__ unsigned long long s_prev;
    __shared__ float s_max, s_sum, s_shift, s_total, s_b2, s_rw;
    __shared__ int s_ncand, s_spred;

    const int b = blockIdx.x;
    const int tid = threadIdx.x, lane = tid & 31, wid = tid >> 5;
    const unsigned lm = (1u << lane) - 1u;

    // ---- stage weights ----
    for (int i = tid; i < 6 * HDIM; i += NT) w1s[i] = W1[i];
    if (tid < HDIM) { b1sh[tid] = b1[tid]; w2sh[tid] = W2[tid]; }
    if (tid == 0) { s_b2 = b2[0]; s_rw = rwp[0]; }

    // ---- pass 1: row -> registers, copy to out, max, unshifted expsum ----
    const float* row = charL + (size_t)b * CDIM;
    float* orow = out + (size_t)b * CDIM;
    const int h = (4 - (int)(((size_t)row >> 2) & 3)) & 3;
    const int nv = (CDIM - h) >> 2;
    const int tl = CDIM - h - 4 * nv;
    const float4* r4 = (const float4*)(row + h);
    const bool ast = ((((size_t)(orow + h)) & 15) == 0);
    float4* o4 = (float4*)(orow + h);

    float headv = -NEGF, tailv = -NEGF;
    float mx = -NEGF, se = 0.f;
    if (tid < h) { headv = row[tid]; orow[tid] = headv; }
    float4 v[4];
    #pragma unroll
    for (int u = 0; u < 4; u++) {
        int i = tid + u * NT;
        if (i < nv) {
            float4 w = r4[i];
            v[u] = w;
            if (ast) o4[i] = w;
            else {
                int j = h + 4 * i;
                orow[j] = w.x; orow[j + 1] = w.y; orow[j + 2] = w.z; orow[j + 3] = w.w;
            }
        } else {
            v[u].x = v[u].y = v[u].z = v[u].w = -NEGF;
        }
    }
    if (tid < tl) { int j = h + 4 * nv + tid; tailv = row[j]; orow[j] = tailv; }

    mx = fmaxf(headv, tailv);
    se += __expf(headv) + __expf(tailv);           // exp(-NEGF)=0
    #pragma unroll
    for (int u = 0; u < 4; u++) {
        float4 w = v[u];
        mx = fmaxf(mx, fmaxf(fmaxf(w.x, w.y), fmaxf(w.z, w.w)));
        se += __expf(w.x) + __expf(w.y) + __expf(w.z) + __expf(w.w);
    }

    float tp = 0.f;
    if (tid < RDIM) {
        float p = 1.f / (1.f + __expf(-radL[(size_t)b * RDIM + tid]));
        rps[tid] = p; tp = p;
    }
    #pragma unroll
    for (int o = 16; o; o >>= 1) {
        mx = fmaxf(mx, __shfl_xor_sync(~0u, mx, o));
        se += __shfl_xor_sync(~0u, se, o);
        tp += __shfl_xor_sync(~0u, tp, o);
    }
    if (lane == 0) { redm[wid] = mx; reds[wid] = se; redt[wid] = tp; }

    // side tasks on distinct warps
    if (tid == 33) {
        const float* st = structL + (size_t)b * SDIM;
        float m = st[0]; float e[SDIM];
        for (int i = 1; i < SDIM; i++) m = fmaxf(m, st[i]);
        float s = 0.f;
        for (int i = 0; i < SDIM; i++) { e[i] = __expf(st[i] - m); s += e[i]; }
        float inv = 1.f / s;
        for (int i = 0; i < SDIM; i++) sprob[i] = e[i] * inv;
    }
    if (tid == 65) {
        const float* sc = scL + (size_t)b * SCBDIM;
        float m = sc[0]; int mi = 0;
        for (int i = 1; i < SCBDIM; i++) { float vv = sc[i]; if (vv > m) { m = vv; mi = i; } }
        s_spred = mi;
    }
    if (tid == 97) {
        const float* sy = styL + (size_t)b * STDIM;
        float vv[STDIM]; float n2 = 0.f;
        for (int i = 0; i < STDIM; i++) { vv[i] = sy[i]; n2 += vv[i] * vv[i]; }
        float n = fmaxf(sqrtf(n2), 1e-12f);
        for (int i = 0; i < STDIM; i++) predn[i] = vv[i] / n;
    }
    __syncthreads();
    if (tid == 0) {
        float m = redm[0], ss = reds[0], tt = redt[0];
        for (int w = 1; w < 8; w++) { m = fmaxf(m, redm[w]); ss += reds[w]; tt += redt[w]; }
        s_max = m; s_sum = ss; s_total = tt;
        s_shift = (m > 60.f) ? m : 0.f;
    }
    __syncthreads();
    if (s_shift != 0.f) {   // overflow-guard; never taken for sane logits
        const float sh = s_shift;
        float se2 = __expf(headv - sh) + __expf(tailv - sh);
        #pragma unroll
        for (int u = 0; u < 4; u++) {
            float4 w = v[u];
            se2 += __expf(w.x - sh) + __expf(w.y - sh) + __expf(w.z - sh) + __expf(w.w - sh);
        }
        #pragma unroll
        for (int o = 16; o; o >>= 1) se2 += __shfl_xor_sync(~0u, se2, o);
        if (lane == 0) reds[wid] = se2;
        __syncthreads();
        if (tid == 0) { float ss = 0.f; for (int w = 0; w < 8; w++) ss += reds[w]; s_sum = ss; }
        __syncthreads();
    }
    const float rowmax = s_max;

    // ---- collect candidates from registers ----
    float dlt = 1.2f;
    int nc;
    for (;;) {
        if (tid == 0) s_ncand = 0;
        __syncthreads();
        const float t = rowmax - dlt;
        append1(headv, tid, t, lane, lm, &s_ncand, cpack);
        #pragma unroll
        for (int u = 0; u < 4; u++) {
            int j = h + 4 * (tid + u * NT);
            append1(v[u].x, j, t, lane, lm, &s_ncand, cpack);
            append1(v[u].y, j + 1, t, lane, lm, &s_ncand, cpack);
            append1(v[u].z, j + 2, t, lane, lm, &s_ncand, cpack);
            append1(v[u].w, j + 3, t, lane, lm, &s_ncand, cpack);
        }
        append1(tailv, h + 4 * nv + tid, t, lane, lm, &s_ncand, cpack);
        __syncthreads();
        nc = s_ncand;
        if (nc >= KTOP) break;
        dlt *= 1.6f;
        __syncthreads();
    }

    // ---- selection ----
    if (nc <= CAP) {
        unsigned long long p0 = (tid < nc) ? cpack[tid] : 0ull;
        unsigned long long p1 = (tid + NT < nc) ? cpack[tid + NT] : 0ull;
        int r0 = 0, r1 = 0;
        for (int j = 0; j < nc; j++) {
            unsigned long long q = cpack[j];
            r0 += (q > p0); r1 += (q > p1);
        }
        if (tid < nc && r0 < KTOP) {
            tIdx[r0] = 0x7FFFFFFF - (int)(p0 & 0xFFFFFFFFu);
            tVal[r0] = key2f((unsigned)(p0 >> 32));
        }
        if (tid + NT < nc && r1 < KTOP) {
            tIdx[r1] = 0x7FFFFFFF - (int)(p1 & 0xFFFFFFFFu);
            tVal[r1] = key2f((unsigned)(p1 >> 32));
        }
    } else {
        // robust fallback (adversarial only): 20 rounds of block argmax over registers
        unsigned long long prev = ~0ull;
        for (int k = 0; k < KTOP; k++) {
            unsigned long long best = 0ull;
            unsigned long long p;
            if (tid < h) { p = packvi(headv, tid); if (p < prev && p > best) best = p; }
            #pragma unroll
            for (int u = 0; u < 4; u++) {
                int i = tid + u * NT;
                if (i < nv) {
                    int j = h + 4 * i;
                    p = packvi(v[u].x, j);     if (p < prev && p > best) best = p;
                    p = packvi(v[u].y, j + 1); if (p < prev && p > best) best = p;
                    p = packvi(v[u].z, j + 2); if (p < prev && p > best) best = p;
                    p = packvi(v[u].w, j + 3); if (p < prev && p > best) best = p;
                }
            }
            if (tid < tl) { p = packvi(tailv, h + 4 * nv + tid); if (p < prev && p > best) best = p; }
            #pragma unroll
            for (int o = 16; o; o >>= 1) {
                unsigned long long q = __shfl_xor_sync(~0u, best, o);
                if (q > best) best = q;
            }
            if (lane == 0) red64[wid] = best;
            __syncthreads();
            if (tid == 0) {
                unsigned long long m = red64[0];
                for (int w = 1; w < 8; w++) if (red64[w] > m) m = red64[w];
                tIdx[k] = 0x7FFFFFFF - (int)(m & 0xFFFFFFFFu);
                tVal[k] = key2f((unsigned)(m >> 32));
                s_prev = m;
            }
            __syncthreads();
            prev = s_prev;
        }
    }
    __syncthreads();

    // ---- features: 8-lane groups for radical dot; threads 160.. do scalars ----
    const int g = tid >> 3, gl = tid & 7;
    const float total = s_total;
    if (g < KTOP) {
        int c = tIdx[g];
        const int2* m2 = (const int2*)(rmask + (size_t)c * RDIM);
        float det = 0.f; int cnt = 0;
        for (int r = gl; r < RDIM / 2; r += 8) {
            int2 mm = m2[r];
            det = fmaf((float)mm.x, rps[2 * r], det);
            det = fmaf((float)mm.y, rps[2 * r + 1], det);
            cnt += mm.x + mm.y;
        }
        #pragma unroll
        for (int o = 4; o; o >>= 1) {
            det += __shfl_xor_sync(~0u, det, o);
            cnt += __shfl_xor_sync(~0u, cnt, o);
        }
        if (gl == 0) {
            feat6[g][0] = det / fmaxf((float)cnt, 1.f);
            feat6[g][1] = (total - det) / fmaxf(total, 1e-6f);
        }
    }
    if (tid >= 160 && tid < 160 + KTOP) {
        int k = tid - 160;
        int c = tIdx[k];
        feat6[k][2] = sprob[slab[c]];
        feat6[k][3] = fabsf((float)(s_spred - sclab[c])) * (1.f / 29.f);
        const float* s6 = sig + (size_t)c * STDIM;
        float n2 = 0.f, dd = 0.f;
        #pragma unroll
        for (int i = 0; i < STDIM; i++) {
            float vv = s6[i];
            n2 += vv * vv;
            dd += predn[i] * vv;
        }
        float nrm = sqrtf(n2);
        feat6[k][4] = (nrm > 1e-6f) ? dd / fmaxf(nrm, 1e-12f) : 0.f;
        feat6[k][5] = __expf(tVal[k] - s_shift) / s_sum;
    }
    __syncthreads();

    // ---- MLP 6->64->1 (8-lane group per candidate) + direct global scatter ----
    if (g < KTOP) {
        float f0 = feat6[g][0], f1 = feat6[g][1], f2 = feat6[g][2];
        float f3 = feat6[g][3], f4 = feat6[g][4], f5 = feat6[g][5];
        float score = 0.f;
        #pragma unroll
        for (int u = 0; u < 8; u++) {
            int j = gl + u * 8;
            float hh = b1sh[j] + f0 * w1s[j] + f1 * w1s[HDIM + j]
                     + f2 * w1s[2 * HDIM + j] + f3 * w1s[3 * HDIM + j]
                     + f4 * w1s[4 * HDIM + j] + f5 * w1s[5 * HDIM + j];
            score += fmaxf(hh, 0.f) * w2sh[j];
        }
        #pragma unroll
        for (int o = 4; o; o >>= 1) score += __shfl_xor_sync(~0u, score, o);
        // ordered after pass-1 copy by the barriers above
        if (gl == 0) orow[tIdx[g]] = tVal[g] + s_rw * (score + s_b2);
    }
}

extern "C" void kernel_launch(void* const* d_in, const int* in_sizes, int n_in,
                              void* d_out, int out_size) {
    (void)n_in; (void)out_size;
    int Bn = in_sizes[0] / CDIM;
    rerank_kernel<<<Bn, NT>>>(
        (const float*)d_in[0],  (const float*)d_in[1],  (const float*)d_in[2],
        (const float*)d_in[3],  (const float*)d_in[4],  (const int*)d_in[5],
        (const int*)d_in[6],    (const int*)d_in[7],    (const float*)d_in[8],
        (const float*)d_in[9],  (const float*)d_in[10], (const float*)d_in[11],
        (const float*)d_in[12], (const float*)d_in[13], (float*)d_out);
}

// round 6
// speedup vs baseline: 1.7289x; 1.7289x over previous
#include <cuda_runtime.h>

#define CDIM 3755
#define RDIM 214
#define SDIM 13
#define SCBDIM 30
#define STDIM 6
#define HDIM 64
#define KTOP 20
#define CAP 512
#define NT 256
#define NEGF 3.4e38f

__device__ __forceinline__ unsigned f2key(float x) {
    unsigned u = __float_as_uint(x);
    return (u & 0x80000000u) ? ~u : (u | 0x80000000u);
}
__device__ __forceinline__ float key2f(unsigned k) {
    return __uint_as_float((k & 0x80000000u) ? (k & 0x7FFFFFFFu) : ~k);
}
__device__ __forceinline__ unsigned long long packvi(float v, int j) {
    return ((unsigned long long)f2key(v) << 32) | (unsigned)(0x7FFFFFFF - j);
}

__global__ void __launch_bounds__(NT) rerank_kernel(
    const float* __restrict__ charL, const float* __restrict__ radL,
    const float* __restrict__ structL, const float* __restrict__ scL,
    const float* __restrict__ styL, const int* __restrict__ rmask,
    const int* __restrict__ slab, const int* __restrict__ sclab,
    const float* __restrict__ sig, const float* __restrict__ W1,
    const float* __restrict__ b1, const float* __restrict__ W2,
    const float* __restrict__ b2, const float* __restrict__ rwp,
    float* __restrict__ out)
{
    __shared__ float4 sh4[(CDIM >> 2) + 2];           // shifted row, 16B-aligned
    __shared__ float shHead[4];
    __shared__ unsigned long long cpack[CAP];
    __shared__ float rps[RDIM];
    __shared__ float w1s[6 * HDIM], b1sh[HDIM], w2sh[HDIM];
    __shared__ float sprob[SDIM], predn[STDIM];
    __shared__ float feat6[KTOP][6];
    __shared__ int tIdx[KTOP];
    __shared__ float tVal[KTOP];
    __shared__ float redm[8], reds[8], redt[8];
    __shared__ unsigned long long red64[8];
    __shared__ unsigned long long s_prev;
    __shared__ float s_max, s_sum, s_shift, s_total, s_b2, s_rw;
    __shared__ int s_ncand, s_spred;

    float* sh = (float*)sh4;
    const int b = blockIdx.x;
    const int tid = threadIdx.x, lane = tid & 31, wid = tid >> 5;

    // ---- stage weights ----
    for (int i = tid; i < 6 * HDIM; i += NT) w1s[i] = W1[i];
    if (tid < HDIM) { b1sh[tid] = b1[tid]; w2sh[tid] = W2[tid]; }
    if (tid == 0) { s_b2 = b2[0]; s_rw = rwp[0]; }

    // ---- pass 1: global -> (smem shifted + out), max, unshifted expsum ----
    const float* row = charL + (size_t)b * CDIM;
    float* orow = out + (size_t)b * CDIM;
    const int h = (4 - (int)(((size_t)row >> 2) & 3)) & 3;
    const int nv = (CDIM - h) >> 2;
    const int tl = CDIM - h - 4 * nv;
    const float4* r4 = (const float4*)(row + h);
    const bool ast = ((((size_t)(orow + h)) & 15) == 0);
    float4* o4 = (float4*)(orow + h);

    float mx = -NEGF, se = 0.f;
    if (tid < h) {
        float v = row[tid]; shHead[tid] = v; orow[tid] = v;
        mx = fmaxf(mx, v); se += __expf(v);
    }
    #pragma unroll
    for (int u = 0; u < 4; u++) {
        int i = tid + u * NT;
        if (i < nv) {
            float4 w = r4[i];
            sh4[i] = w;
            if (ast) o4[i] = w;
            else {
                int j = h + 4 * i;
                orow[j] = w.x; orow[j + 1] = w.y; orow[j + 2] = w.z; orow[j + 3] = w.w;
            }
            mx = fmaxf(mx, fmaxf(fmaxf(w.x, w.y), fmaxf(w.z, w.w)));
            se += __expf(w.x) + __expf(w.y) + __expf(w.z) + __expf(w.w);
        }
    }
    if (tid < tl) {
        int k = 4 * nv + tid;
        float v = row[h + k]; sh[k] = v; orow[h + k] = v;
        mx = fmaxf(mx, v); se += __expf(v);
    }
    float tp = 0.f;
    if (tid < RDIM) {
        float p = 1.f / (1.f + __expf(-radL[(size_t)b * RDIM + tid]));
        rps[tid] = p; tp = p;
    }
    #pragma unroll
    for (int o = 16; o; o >>= 1) {
        mx = fmaxf(mx, __shfl_xor_sync(~0u, mx, o));
        se += __shfl_xor_sync(~0u, se, o);
        tp += __shfl_xor_sync(~0u, tp, o);
    }
    if (lane == 0) { redm[wid] = mx; reds[wid] = se; redt[wid] = tp; }

    // side tasks on distinct warps
    if (tid == 33) {
        const float* st = structL + (size_t)b * SDIM;
        float m = st[0]; float e[SDIM];
        for (int i = 1; i < SDIM; i++) m = fmaxf(m, st[i]);
        float s = 0.f;
        for (int i = 0; i < SDIM; i++) { e[i] = __expf(st[i] - m); s += e[i]; }
        float inv = 1.f / s;
        for (int i = 0; i < SDIM; i++) sprob[i] = e[i] * inv;
    }
    if (tid == 65) {
        const float* sc = scL + (size_t)b * SCBDIM;
        float m = sc[0]; int mi = 0;
        for (int i = 1; i < SCBDIM; i++) { float vv = sc[i]; if (vv > m) { m = vv; mi = i; } }
        s_spred = mi;
    }
    if (tid == 97) {
        const float* sy = styL + (size_t)b * STDIM;
        float vv[STDIM]; float n2 = 0.f;
        for (int i = 0; i < STDIM; i++) { vv[i] = sy[i]; n2 += vv[i] * vv[i]; }
        float n = fmaxf(sqrtf(n2), 1e-12f);
        for (int i = 0; i < STDIM; i++) predn[i] = vv[i] / n;
    }
    __syncthreads();
    if (tid == 0) {
        float m = redm[0], ss = reds[0], tt = redt[0];
        for (int w = 1; w < 8; w++) { m = fmaxf(m, redm[w]); ss += reds[w]; tt += redt[w]; }
        s_max = m; s_sum = ss; s_total = tt;
        s_shift = (m > 60.f) ? m : 0.f;
    }
    __syncthreads();
    if (s_shift != 0.f) {   // overflow-guard; never taken for sane logits
        const float shv = s_shift;
        float se2 = 0.f;
        for (int k = tid; k < CDIM - h; k += NT) se2 += __expf(sh[k] - shv);
        if (tid < h) se2 += __expf(shHead[tid] - shv);
        #pragma unroll
        for (int o = 16; o; o >>= 1) se2 += __shfl_xor_sync(~0u, se2, o);
        if (lane == 0) reds[wid] = se2;
        __syncthreads();
        if (tid == 0) { float ss = 0.f; for (int w = 0; w < 8; w++) ss += reds[w]; s_sum = ss; }
        __syncthreads();
    }
    const float rowmax = s_max;

    // ---- collect candidates: LDS.128 + count-scan compaction ----
    float dlt = 1.2f;
    int nc;
    for (;;) {
        if (tid == 0) s_ncand = 0;
        __syncthreads();
        const float t = rowmax - dlt;
        #pragma unroll
        for (int u = 0; u < 5; u++) {
            float4 w; int j0; int c;
            if (u < 4) {
                int i = tid + u * NT;
                if (i < nv) { w = sh4[i]; j0 = h + 4 * i; }
                else { w.x = w.y = w.z = w.w = -NEGF; j0 = 0; }
                c = (w.x >= t) + (w.y >= t) + (w.z >= t) + (w.w >= t);
            } else {
                // head (lanes tid<h) and tail (tid in [32, 32+tl))
                if (tid < h) { w.x = shHead[tid]; j0 = tid; }
                else if (tid >= 32 && tid - 32 < tl) { w.x = sh[4 * nv + tid - 32]; j0 = h + 4 * nv + tid - 32; }
                else { w.x = -NEGF; j0 = 0; }
                w.y = w.z = w.w = -NEGF;
                c = (w.x >= t);
            }
            int incl = c;
            #pragma unroll
            for (int o = 1; o < 32; o <<= 1) {
                int q = __shfl_up_sync(~0u, incl, o);
                if (lane >= o) incl += q;
            }
            int tot = __shfl_sync(~0u, incl, 31);
            if (tot) {
                int base = 0;
                if (lane == 31) base = atomicAdd(&s_ncand, tot);
                base = __shfl_sync(~0u, base, 31);
                int pos = base + incl - c;
                if (w.x >= t) { if (pos < CAP) cpack[pos] = packvi(w.x, j0); pos++; }
                if (w.y >= t) { if (pos < CAP) cpack[pos] = packvi(w.y, j0 + 1); pos++; }
                if (w.z >= t) { if (pos < CAP) cpack[pos] = packvi(w.z, j0 + 2); pos++; }
                if (w.w >= t) { if (pos < CAP) cpack[pos] = packvi(w.w, j0 + 3); }
            }
        }
        __syncthreads();
        nc = s_ncand;
        if (nc >= KTOP) break;
        dlt *= 1.6f;
        __syncthreads();
    }

    // ---- selection ----
    if (nc <= CAP) {
        // parallel rank; ties: lower index wins (encoded in pack)
        unsigned long long p0 = (tid < nc) ? cpack[tid] : 0ull;
        unsigned long long p1 = (tid + NT < nc) ? cpack[tid + NT] : 0ull;
        int r0 = 0, r1 = 0;
        for (int j = 0; j < nc; j++) {
            unsigned long long q = cpack[j];
            r0 += (q > p0); r1 += (q > p1);
        }
        if (tid < nc && r0 < KTOP) {
            tIdx[r0] = 0x7FFFFFFF - (int)(p0 & 0xFFFFFFFFu);
            tVal[r0] = key2f((unsigned)(p0 >> 32));
        }
        if (tid + NT < nc && r1 < KTOP) {
            tIdx[r1] = 0x7FFFFFFF - (int)(p1 & 0xFFFFFFFFu);
            tVal[r1] = key2f((unsigned)(p1 >> 32));
        }
    } else {
        // robust fallback (adversarial only): 20 rounds of block argmax over smem
        unsigned long long prev = ~0ull;
        for (int k = 0; k < KTOP; k++) {
            unsigned long long best = 0ull;
            unsigned long long p;
            if (tid < h) { p = packvi(shHead[tid], tid); if (p < prev && p > best) best = p; }
            for (int kk = tid; kk < CDIM - h; kk += NT) {
                p = packvi(sh[kk], h + kk);
                if (p < prev && p > best) best = p;
            }
            #pragma unroll
            for (int o = 16; o; o >>= 1) {
                unsigned long long q = __shfl_xor_sync(~0u, best, o);
                if (q > best) best = q;
            }
            if (lane == 0) red64[wid] = best;
            __syncthreads();
            if (tid == 0) {
                unsigned long long m = red64[0];
                for (int w = 1; w < 8; w++) if (red64[w] > m) m = red64[w];
                tIdx[k] = 0x7FFFFFFF - (int)(m & 0xFFFFFFFFu);
                tVal[k] = key2f((unsigned)(m >> 32));
                s_prev = m;
            }
            __syncthreads();
            prev = s_prev;
        }
    }
    __syncthreads();

    // ---- features: 8-lane groups for radical dot; threads 160.. do scalars ----
    const int g = tid >> 3, gl = tid & 7;
    const float total = s_total;
    if (g < KTOP) {
        int c = tIdx[g];
        const int2* m2 = (const int2*)(rmask + (size_t)c * RDIM);
        float det = 0.f; int cnt = 0;
        for (int r = gl; r < RDIM / 2; r += 8) {
            int2 mm = m2[r];
            det = fmaf((float)mm.x, rps[2 * r], det);
            det = fmaf((float)mm.y, rps[2 * r + 1], det);
            cnt += mm.x + mm.y;
        }
        #pragma unroll
        for (int o = 4; o; o >>= 1) {
            det += __shfl_xor_sync(~0u, det, o);
            cnt += __shfl_xor_sync(~0u, cnt, o);
        }
        if (gl == 0) {
            feat6[g][0] = det / fmaxf((float)cnt, 1.f);
            feat6[g][1] = (total - det) / fmaxf(total, 1e-6f);
        }
    }
    if (tid >= 160 && tid < 160 + KTOP) {
        int k = tid - 160;
        int c = tIdx[k];
        feat6[k][2] = sprob[slab[c]];
        feat6[k][3] = fabsf((float)(s_spred - sclab[c])) * (1.f / 29.f);
        const float* s6 = sig + (size_t)c * STDIM;
        float n2 = 0.f, dd = 0.f;
        #pragma unroll
        for (int i = 0; i < STDIM; i++) {
            float vv = s6[i];
            n2 += vv * vv;
            dd += predn[i] * vv;
        }
        float nrm = sqrtf(n2);
        feat6[k][4] = (nrm > 1e-6f) ? dd / fmaxf(nrm, 1e-12f) : 0.f;
        feat6[k][5] = __expf(tVal[k] - s_shift) / s_sum;
    }
    __syncthreads();

    // ---- MLP 6->64->1 (8-lane group per candidate) + direct global scatter ----
    if (g < KTOP) {
        float f0 = feat6[g][0], f1 = feat6[g][1], f2 = feat6[g][2];
        float f3 = feat6[g][3], f4 = feat6[g][4], f5 = feat6[g][5];
        float score = 0.f;
        #pragma unroll
        for (int u = 0; u < 8; u++) {
            int j = gl + u * 8;
            float hh = b1sh[j] + f0 * w1s[j] + f1 * w1s[HDIM + j]
                     + f2 * w1s[2 * HDIM + j] + f3 * w1s[3 * HDIM + j]
                     + f4 * w1s[4 * HDIM + j] + f5 * w1s[5 * HDIM + j];
            score += fmaxf(hh, 0.f) * w2sh[j];
        }
        #pragma unroll
        for (int o = 4; o; o >>= 1) score += __shfl_xor_sync(~0u, score, o);
        // ordered after the pass-1 copy by the intervening __syncthreads
        if (gl == 0) orow[tIdx[g]] = tVal[g] + s_rw * (score + s_b2);
    }
}

extern "C" void kernel_launch(void* const* d_in, const int* in_sizes, int n_in,
                              void* d_out, int out_size) {
    (void)n_in; (void)out_size;
    int Bn = in_sizes[0] / CDIM;
    rerank_kernel<<<Bn, NT>>>(
        (const float*)d_in[0],  (const float*)d_in[1],  (const float*)d_in[2],
        (const float*)d_in[3],  (const float*)d_in[4],  (const int*)d_in[5],
        (const int*)d_in[6],    (const int*)d_in[7],    (const float*)d_in[8],
        (const float*)d_in[9],  (const float*)d_in[10], (const float*)d_in[11],
        (const float*)d_in[12], (const float*)d_in[13], (float*)d_out);
}